// round 15
// baseline (speedup 1.0000x reference)
#include <cuda_runtime.h>
#include <cuda_bf16.h>
#include <cstdint>
#include <cstring>

#define BB 64
#define TT 128
#define CC 4096
#define HH 32
#define HSD 128
__device__ const float SCALE = 0.17677669529663687f;

// device-global scratch
__device__ __nv_bfloat16 g_Xhi[(size_t)8192*4096];
__device__ __nv_bfloat16 g_Xlo[(size_t)8192*4096];
__device__ __nv_bfloat16 g_Whi[(size_t)3*4096*4096];
__device__ __nv_bfloat16 g_Wlo[(size_t)3*4096*4096];
__device__ __nv_bfloat16 g_Phi[(size_t)4096*4096];
__device__ __nv_bfloat16 g_Plo[(size_t)4096*4096];
__device__ __nv_bfloat16 g_AThi[(size_t)8192*4096];
__device__ __nv_bfloat16 g_ATlo[(size_t)8192*4096];
__device__ __nv_bfloat16 g_Qhi[(size_t)BB*HH*TT*HSD];
__device__ __nv_bfloat16 g_Qlo[(size_t)BB*HH*TT*HSD];
__device__ __nv_bfloat16 g_Khi[(size_t)BB*HH*TT*HSD];
__device__ __nv_bfloat16 g_Klo[(size_t)BB*HH*TT*HSD];
__device__ __nv_bfloat16 g_VThi[(size_t)BB*HH*TT*HSD];   // [b,h][s][t]
__device__ __nv_bfloat16 g_VTlo[(size_t)BB*HH*TT*HSD];

__device__ __forceinline__ uint32_t smem_u32(const void* p){
    uint32_t a;
    asm("{ .reg .u64 t; cvta.to.shared.u64 t, %1; cvt.u32.u64 %0, t; }" : "=r"(a) : "l"(p));
    return a;
}
__device__ __forceinline__ void cp16g(const void* smem_dst, const void* gsrc){
    uint32_t s = (uint32_t)__cvta_generic_to_shared(smem_dst);
    asm volatile("cp.async.cg.shared.global [%0], [%1], 16;" :: "r"(s), "l"(gsrc));
}
#define CP_COMMIT() asm volatile("cp.async.commit_group;")
#define CP_WAIT0()  asm volatile("cp.async.wait_group 0;")
#define MBAR_INIT(a, c) \
    asm volatile("mbarrier.init.shared.b64 [%0], %1;" :: "r"(a), "r"(c) : "memory")
#define MBAR_ARRIVE(a) \
    asm volatile("mbarrier.arrive.shared.b64 _, [%0];" :: "r"(a) : "memory")
#define CPA_ARRIVE(a) \
    asm volatile("cp.async.mbarrier.arrive.noinc.shared::cta.b64 [%0];" :: "r"(a) : "memory")
#define MBAR_WAIT(a, ph) do{ unsigned _d=0; while(!_d){ \
    asm volatile("{\n\t.reg .pred p;\n\t" \
        "mbarrier.try_wait.parity.acquire.cta.shared::cta.b64 p, [%1], %2;\n\t" \
        "selp.b32 %0, 1, 0, p;\n\t}" : "=r"(_d) : "r"(a), "r"(ph) : "memory"); } }while(0)
#define BARC(id, n) asm volatile("bar.sync %0, %1;" :: "r"(id), "r"(n) : "memory")

#define LDSM4(r0,r1,r2,r3, addr) \
    asm volatile("ldmatrix.sync.aligned.m8n8.x4.shared.b16 {%0,%1,%2,%3}, [%4];" \
        : "=r"(r0), "=r"(r1), "=r"(r2), "=r"(r3) : "r"(addr))

// bf16 m16n8k16 MMA
__device__ __forceinline__ void mma_bf16(float* d, const uint32_t* a, uint32_t b0, uint32_t b1){
    asm volatile("mma.sync.aligned.m16n8k16.row.col.f32.bf16.bf16.f32 "
        "{%0,%1,%2,%3},{%4,%5,%6,%7},{%8,%9},{%0,%1,%2,%3};"
        : "+f"(d[0]), "+f"(d[1]), "+f"(d[2]), "+f"(d[3])
        : "r"(a[0]), "r"(a[1]), "r"(a[2]), "r"(a[3]), "r"(b0), "r"(b1));
}
__device__ __forceinline__ void mma3b(float* d, const uint32_t* ah, const uint32_t* al,
                                      uint32_t bh0, uint32_t bh1, uint32_t bl0, uint32_t bl1){
    mma_bf16(d, al, bh0, bh1);
    mma_bf16(d, ah, bl0, bl1);
    mma_bf16(d, ah, bh0, bh1);
}

__device__ __forceinline__ uint32_t pack2(float a, float b){
    __nv_bfloat162 t(__float2bfloat16(a), __float2bfloat16(b));  // x=low, y=high
    uint32_t u; memcpy(&u, &t, 4); return u;
}
__device__ __forceinline__ void split2(float a, float b, uint32_t& hi, uint32_t& lo){
    __nv_bfloat16 h0 = __float2bfloat16(a), h1 = __float2bfloat16(b);
    hi = pack2(a, b);
    lo = pack2(a - __bfloat162float(h0), b - __bfloat162float(h1));
}

// -------- prep: flat fp32 -> bf16 hi/lo.  0: x -> X   1: wp -> P --------
template<int MODE>
__global__ __launch_bounds__(256)
void conv_flat(const float* __restrict__ src)
{
    size_t i = (size_t)blockIdx.x * 256 + threadIdx.x;
    const float4* s4 = (const float4*)src;
    float4 a = s4[2*i], b = s4[2*i+1];
    float v[8] = {a.x,a.y,a.z,a.w,b.x,b.y,b.z,b.w};
    alignas(16) __nv_bfloat16 h[8], l[8];
    #pragma unroll
    for (int j=0;j<8;j++){
        h[j] = __float2bfloat16(v[j]);
        l[j] = __float2bfloat16(v[j] - __bfloat162float(h[j]));
    }
    __nv_bfloat16* dh = (MODE==0) ? g_Xhi : g_Phi;
    __nv_bfloat16* dl = (MODE==0) ? g_Xlo : g_Plo;
    ((uint4*)dh)[i] = *(const uint4*)h;
    ((uint4*)dl)[i] = *(const uint4*)l;
}

// -------- prep: w[h][c][s] -> W[z][n=h*128+s][k=c] transpose-split --------
__global__ __launch_bounds__(256)
void conv_wT(const float* __restrict__ wq, const float* __restrict__ wk,
             const float* __restrict__ wv)
{
    __shared__ float tile[32][33];
    const int st = blockIdx.x, ct = blockIdx.y;
    const int z = blockIdx.z >> 5, h = blockIdx.z & 31;
    const float* w = (z==0 ? wq : (z==1 ? wk : wv)) + (size_t)h*CC*HSD;
    const int tx = threadIdx.x, ty = threadIdx.y;
    #pragma unroll
    for (int j=0;j<4;j++)
        tile[ty+8*j][tx] = w[(size_t)(ct*32 + ty+8*j)*HSD + st*32 + tx];
    __syncthreads();
    __nv_bfloat16* oh = g_Whi + (size_t)z*CC*CC;
    __nv_bfloat16* ol = g_Wlo + (size_t)z*CC*CC;
    #pragma unroll
    for (int j=0;j<4;j++){
        int sI = st*32 + ty+8*j, c = ct*32 + tx;
        float v = tile[tx][ty+8*j];
        __nv_bfloat16 hv = __float2bfloat16(v);
        __nv_bfloat16 lv = __float2bfloat16(v - __bfloat162float(hv));
        size_t o = (size_t)(h*128 + sI)*CC + c;
        oh[o] = hv; ol[o] = lv;
    }
}

// ---------------------------------------------------------------------------
// PERSISTENT warp-specialized bf16 3-term GEMM, ldmatrix fragments.
// CTA tile 128x128, K-tile 64, 2 mbarrier stages running continuously across
// tiles; dedicated sT region for the V transpose. 384 threads.
// MODE 0: X @ W[z] -> Qhi/lo, Khi/lo or VT hi/lo.   MODE 1: AT @ P + bias -> C.
// ---------------------------------------------------------------------------
#define PITCH 36
#define ARRW  (128*PITCH)
#define NSTG  2
#define STGU  (4*ARRW)
#define FULLB(s)  (sb + 16*(s))
#define EMPTYB(s) (sb + 16*(s) + 8)

template<int MODE>
__global__ __launch_bounds__(384, 1)
void gemm_bf(const float* __restrict__ bias, float* __restrict__ Cout)
{
    extern __shared__ uint32_t sm[];
    const uint32_t sb = smem_u32(sm);
    const int tid = threadIdx.x;
    const int NT = (MODE==0) ? 6144 : 2048;

    if (tid==0){
        #pragma unroll
        for (int s=0;s<NSTG;s++){ MBAR_INIT(FULLB(s), 128); MBAR_INIT(EMPTYB(s), 256); }
    }
    __syncthreads();

    const int NKT = CC/64;

    if (tid >= 256){
        // ---------------- producers (128 threads), continuous ring ----------
        const int pt = tid - 256;
        int ph[NSTG] = {1,1};
        int s = 0;
        for (int t = blockIdx.x; t < NT; t += gridDim.x){
            const int p = (MODE==0) ? (t & 2047) : t;
            const int z = (MODE==0) ? (t >> 11) : 0;
            const int pid = p >> 8, rem = p & 255;
            const int m0 = (pid*8 + (rem & 7))*128, n0 = (rem >> 3)*128;
            const __nv_bfloat16 *Ah, *Al, *Bh, *Bl;
            if (MODE==0){ Ah=g_Xhi; Al=g_Xlo; Bh=g_Whi+(size_t)z*CC*CC; Bl=g_Wlo+(size_t)z*CC*CC; }
            else        { Ah=g_AThi; Al=g_ATlo; Bh=g_Phi; Bl=g_Plo; }
            for (int kt=0; kt<NKT; kt++){
                MBAR_WAIT(EMPTYB(s), ph[s]); ph[s] ^= 1;
                uint32_t* base = sm + 256 + s*STGU;
                const size_t kO = (size_t)kt*64;
                #pragma unroll
                for (int j=0;j<32;j++){
                    int id = pt + j*128;
                    int arr = id >> 10;
                    int c   = id & 1023;
                    int row = c >> 3, c16 = c & 7;
                    uint32_t* dst = base + arr*ARRW + row*PITCH + c16*4;
                    const __nv_bfloat16* gp =
                        (arr==0) ? Ah + (size_t)(m0+row)*CC + kO + c16*8 :
                        (arr==1) ? Al + (size_t)(m0+row)*CC + kO + c16*8 :
                        (arr==2) ? Bh + (size_t)(n0+row)*CC + kO + c16*8 :
                                   Bl + (size_t)(n0+row)*CC + kO + c16*8;
                    cp16g(dst, gp);
                }
                CPA_ARRIVE(FULLB(s));
                s ^= 1;
            }
        }
        return;
    }

    // ---------------- consumers (256 threads, 8 warps) ----------------
    const int warp = tid>>5, lane = tid&31, g = lane>>2, tg = lane&3;
    const int wm = (warp>>1)*32, wn = (warp&1)*64;

    const int lr = lane & 15;
    const int lc = lane >> 4;
    const int bn = (lane & 7) + ((lane & 16) ? 8 : 0);
    const int bc = (lane >> 3) & 1;
    const uint32_t aoff0 = (uint32_t)(((wm      + lr)*PITCH + lc*4)*4);
    const uint32_t aoff1 = (uint32_t)(((wm + 16 + lr)*PITCH + lc*4)*4);
    uint32_t boff[4];
    #pragma unroll
    for (int p=0;p<4;p++) boff[p] = (uint32_t)(((wn + p*16 + bn)*PITCH + bc*4)*4);
    const uint32_t dbase = sb + 1024;
    const uint32_t A4 = ARRW*4;

    int phf[NSTG] = {0,0};
    int s = 0;
    for (int t = blockIdx.x; t < NT; t += gridDim.x){
        const int p = (MODE==0) ? (t & 2047) : t;
        const int z = (MODE==0) ? (t >> 11) : 0;
        const int pid = p >> 8, rem = p & 255;
        const int mt = pid*8 + (rem & 7), nt = rem >> 3;
        const int m0 = mt*128, n0 = nt*128;

        float acc[2][8][4];
        #pragma unroll
        for (int a=0;a<2;a++)
            #pragma unroll
            for (int b=0;b<8;b++)
                #pragma unroll
                for (int c=0;c<4;c++) acc[a][b][c] = 0.f;

        for (int kt=0; kt<NKT; kt++){
            MBAR_WAIT(FULLB(s), phf[s]); phf[s] ^= 1;
            const uint32_t stgb = dbase + s*(STGU*4);
            #pragma unroll
            for (int kk=0; kk<4; kk++){
                const uint32_t kb = kk*32;
                uint32_t ah0[4], ah1[4], al0[4], al1[4];
                LDSM4(ah0[0],ah0[1],ah0[2],ah0[3], stgb + aoff0 + kb);
                LDSM4(ah1[0],ah1[1],ah1[2],ah1[3], stgb + aoff1 + kb);
                LDSM4(al0[0],al0[1],al0[2],al0[3], stgb + A4 + aoff0 + kb);
                LDSM4(al1[0],al1[1],al1[2],al1[3], stgb + A4 + aoff1 + kb);
                uint32_t bh[4][4], bl[4][4];
                #pragma unroll
                for (int p2=0;p2<4;p2++){
                    LDSM4(bh[p2][0],bh[p2][1],bh[p2][2],bh[p2][3], stgb + 2*A4 + boff[p2] + kb);
                    LDSM4(bl[p2][0],bl[p2][1],bl[p2][2],bl[p2][3], stgb + 3*A4 + boff[p2] + kb);
                }
                if (kk==3) MBAR_ARRIVE(EMPTYB(s));
                #pragma unroll
                for (int p2=0;p2<4;p2++){
                    mma3b(acc[0][2*p2  ], ah0, al0, bh[p2][0], bh[p2][1], bl[p2][0], bl[p2][1]);
                    mma3b(acc[1][2*p2  ], ah1, al1, bh[p2][0], bh[p2][1], bl[p2][0], bl[p2][1]);
                    mma3b(acc[0][2*p2+1], ah0, al0, bh[p2][2], bh[p2][3], bl[p2][2], bl[p2][3]);
                    mma3b(acc[1][2*p2+1], ah1, al1, bh[p2][2], bh[p2][3], bl[p2][2], bl[p2][3]);
                }
            }
            s ^= 1;
        }

        if (MODE==0){
            const int b = m0 >> 7;
            const int head = nt;
            if (z < 2){
                __nv_bfloat16* dh = (z==0) ? g_Qhi : g_Khi;
                __nv_bfloat16* dl = (z==0) ? g_Qlo : g_Klo;
                #pragma unroll
                for (int mi=0; mi<2; mi++){
                    #pragma unroll
                    for (int ni=0; ni<8; ni++){
                        int tt = (wm + mi*16 + g);
                        int sc = wn + ni*8 + tg*2;
                        size_t idx = (((size_t)(b*HH + head))*TT + tt)*HSD + sc;
                        uint32_t h0, l0, h1, l1;
                        split2(acc[mi][ni][0], acc[mi][ni][1], h0, l0);
                        split2(acc[mi][ni][2], acc[mi][ni][3], h1, l1);
                        *(uint32_t*)(dh + idx) = h0;
                        *(uint32_t*)(dl + idx) = l0;
                        *(uint32_t*)(dh + idx + 8*HSD) = h1;
                        *(uint32_t*)(dl + idx + 8*HSD) = l1;
                    }
                }
            } else {
                // V: transpose through DEDICATED sT region (no producer conflict)
                float* sT = (float*)(sm + 256 + NSTG*STGU);
                BARC(1, 256);
                #pragma unroll
                for (int mi=0; mi<2; mi++){
                    #pragma unroll
                    for (int ni=0; ni<8; ni++){
                        int tt = wm + mi*16 + g;
                        int sc = wn + ni*8 + tg*2;
                        sT[sc*132 + tt]       = acc[mi][ni][0];
                        sT[(sc+1)*132 + tt]   = acc[mi][ni][1];
                        sT[sc*132 + tt+8]     = acc[mi][ni][2];
                        sT[(sc+1)*132 + tt+8] = acc[mi][ni][3];
                    }
                }
                BARC(1, 256);
                __nv_bfloat16* vh = g_VThi + (((size_t)(b*HH + head))*HSD)*TT;
                __nv_bfloat16* vl = g_VTlo + (((size_t)(b*HH + head))*HSD)*TT;
                #pragma unroll
                for (int i=0;i<16;i++){
                    int idx = tid + i*256;
                    int sc = idx>>5, t4 = (idx&31)*4;
                    float4 v = *(const float4*)&sT[sc*132 + t4];
                    uint32_t h0,l0,h1,l1;
                    split2(v.x, v.y, h0, l0);
                    split2(v.z, v.w, h1, l1);
                    uint2 hv; hv.x = h0; hv.y = h1;
                    uint2 lv; lv.x = l0; lv.y = l1;
                    *(uint2*)(vh + (size_t)sc*TT + t4) = hv;
                    *(uint2*)(vl + (size_t)sc*TT + t4) = lv;
                }
            }
        } else {
            #pragma unroll
            for (int mi=0; mi<2; mi++){
                #pragma unroll
                for (int ni=0; ni<8; ni++){
                    int mrow = m0 + wm + mi*16 + g;
                    int ncol = n0 + wn + ni*8 + tg*2;
                    float bv0 = bias[ncol], bv1 = bias[ncol+1];
                    float* pD = Cout + (size_t)mrow*CC + ncol;
                    pD[0] = acc[mi][ni][0] + bv0; pD[1] = acc[mi][ni][1] + bv1;
                    pD[8*CC] = acc[mi][ni][2] + bv0; pD[8*CC+1] = acc[mi][ni][3] + bv1;
                }
            }
        }
    }
}

// ---------------------------------------------------------------------------
// Attention, all-bf16 3-term: QK^T -> softmax over QUERY axis -> P@V.
// ---------------------------------------------------------------------------
#define APITCH 68
#define AARR   (128*APITCH)
__global__ __launch_bounds__(256)
void attn_kernel()
{
    extern __shared__ uint32_t smu[];
    const uint32_t sb = smem_u32(smu);
    float* sW = (float*)(smu + 4*AARR);     // [t][132]

    const int tid = threadIdx.x;
    const int bid = blockIdx.x;
    const int bh = bid;
    const __nv_bfloat16* qh = g_Qhi + (size_t)bh*TT*HSD;
    const __nv_bfloat16* ql = g_Qlo + (size_t)bh*TT*HSD;
    const __nv_bfloat16* kh = g_Khi + (size_t)bh*TT*HSD;
    const __nv_bfloat16* kl = g_Klo + (size_t)bh*TT*HSD;

    #pragma unroll
    for (int i=0;i<32;i++){
        int idx = tid + i*256;
        int arr = idx >> 11;
        int c   = idx & 2047;
        int row = c >> 4, ch = c & 15;
        uint32_t* dst = smu + arr*AARR + row*APITCH + ch*4;
        const __nv_bfloat16* gp =
            (arr==0) ? qh + (size_t)row*HSD + ch*8 :
            (arr==1) ? ql + (size_t)row*HSD + ch*8 :
            (arr==2) ? kh + (size_t)row*HSD + ch*8 :
                       kl + (size_t)row*HSD + ch*8;
        cp16g(dst, gp);
    }
    CP_COMMIT(); CP_WAIT0();
    __syncthreads();

    const int warp = tid>>5, lane = tid&31, g = lane>>2, tg = lane&3;
    const int wm = (warp>>1)*32, wn = (warp&1)*64;
    const int lr = lane & 15;
    const int lc = lane >> 4;
    const int bn = (lane & 7) + ((lane & 16) ? 8 : 0);
    const int bc = (lane >> 3) & 1;
    const uint32_t aoff0 = (uint32_t)(((wm      + lr)*APITCH + lc*4)*4);
    const uint32_t aoff1 = (uint32_t)(((wm + 16 + lr)*APITCH + lc*4)*4);
    uint32_t boff[4];
    #pragma unroll
    for (int p=0;p<4;p++) boff[p] = (uint32_t)(((wn + p*16 + bn)*APITCH + bc*4)*4);
    const uint32_t A1 = AARR*4;

    // ---- QK^T ----
    {
        float acc[2][8][4];
        #pragma unroll
        for (int a=0;a<2;a++)
            #pragma unroll
            for (int c2=0;c2<8;c2++)
                #pragma unroll
                for (int d2=0;d2<4;d2++) acc[a][c2][d2]=0.f;
        #pragma unroll
        for (int kk=0; kk<8; kk++){
            const uint32_t kb = kk*32;
            uint32_t ah0[4], ah1[4], al0[4], al1[4];
            LDSM4(ah0[0],ah0[1],ah0[2],ah0[3], sb + aoff0 + kb);
            LDSM4(ah1[0],ah1[1],ah1[2],ah1[3], sb + aoff1 + kb);
            LDSM4(al0[0],al0[1],al0[2],al0[3], sb + A1 + aoff0 + kb);
            LDSM4(al1[0],al1[1],al1[2],al1[3], sb + A1 + aoff1 + kb);
            uint32_t bhf[4][4], blf[4][4];
            #pragma unroll
            for (int p=0;p<4;p++){
                LDSM4(bhf[p][0],bhf[p][1],bhf[p][2],bhf[p][3], sb + 2*A1 + boff[p] + kb);
                LDSM4(blf[p][0],blf[p][1],blf[p][2],blf[p][3], sb + 3*A1 + boff[p] + kb);
            }
            #pragma unroll
            for (int p=0;p<4;p++){
                mma3b(acc[0][2*p  ], ah0, al0, bhf[p][0], bhf[p][1], blf[p][0], blf[p][1]);
                mma3b(acc[1][2*p  ], ah1, al1, bhf[p][0], bhf[p][1], blf[p][0], blf[p][1]);
                mma3b(acc[0][2*p+1], ah0, al0, bhf[p][2], bhf[p][3], blf[p][2], blf[p][3]);
                mma3b(acc[1][2*p+1], ah1, al1, bhf[p][2], bhf[p][3], blf[p][2], blf[p][3]);
            }
        }
        #pragma unroll
        for (int mi=0; mi<2; mi++){
            #pragma unroll
            for (int ni=0; ni<8; ni++){
                int r = wm + mi*16 + g;
                int c = wn + ni*8 + tg*2;
                sW[r*132+c]       = acc[mi][ni][0]*SCALE;
                sW[r*132+c+1]     = acc[mi][ni][1]*SCALE;
                sW[(r+8)*132+c]   = acc[mi][ni][2]*SCALE;
                sW[(r+8)*132+c+1] = acc[mi][ni][3]*SCALE;
            }
        }
    }
    __syncthreads();

    if (tid < 128){
        const int u = tid;
        float mx = -1e30f;
        for (int t=0;t<128;t++) mx = fmaxf(mx, sW[t*132+u]);
        float ssum = 0.f;
        for (int t=0;t<128;t++){ float e = __expf(sW[t*132+u]-mx); sW[t*132+u]=e; ssum+=e; }
        float inv = 1.f/ssum;
        for (int t=0;t<128;t++) sW[t*132+u] *= inv;
    } else {
        const int lt = tid - 128;
        const __nv_bfloat16* vh = g_VThi + (size_t)bh*HSD*TT;
        const __nv_bfloat16* vl = g_VTlo + (size_t)bh*HSD*TT;
        #pragma unroll
        for (int i=0;i<32;i++){
            int idx = lt + i*128;
            int arr = idx >> 11;
            int c   = idx & 2047;
            int row = c >> 4, ch = c & 15;
            uint32_t* dst = smu + arr*AARR + row*APITCH + ch*4;
            const __nv_bfloat16* gp = (arr==0)
                ? vh + (size_t)row*TT + ch*8
                : vl + (size_t)row*TT + ch*8;
            cp16g(dst, gp);
        }
        CP_COMMIT(); CP_WAIT0();
    }
    __syncthreads();

    // convert W f32 -> bf16 hi/lo into K region (arrays 2,3)
    {
        int r = tid >> 1, half = tid & 1;
        uint32_t* wh = smu + 2*AARR + r*APITCH + half*32;
        uint32_t* wl = smu + 3*AARR + r*APITCH + half*32;
        const float* src = sW + r*132 + half*64;
        #pragma unroll
        for (int j=0;j<32;j++){
            uint32_t hi, lo;
            split2(src[2*j], src[2*j+1], hi, lo);
            wh[j] = hi; wl[j] = lo;
        }
    }
    __syncthreads();

    // ---- P@V ----
    {
        float acc[2][8][4];
        #pragma unroll
        for (int a=0;a<2;a++)
            #pragma unroll
            for (int c2=0;c2<8;c2++)
                #pragma unroll
                for (int d2=0;d2<4;d2++) acc[a][c2][d2]=0.f;
        #pragma unroll
        for (int kk=0; kk<8; kk++){
            const uint32_t kb = kk*32;
            uint32_t ah0[4], ah1[4], al0[4], al1[4];
            LDSM4(ah0[0],ah0[1],ah0[2],ah0[3], sb + 2*A1 + aoff0 + kb);
            LDSM4(ah1[0],ah1[1],ah1[2],ah1[3], sb + 2*A1 + aoff1 + kb);
            LDSM4(al0[0],al0[1],al0[2],al0[3], sb + 3*A1 + aoff0 + kb);
            LDSM4(al1[0],al1[1],al1[2],al1[3], sb + 3*A1 + aoff1 + kb);
            uint32_t bhf[4][4], blf[4][4];
            #pragma unroll
            for (int p=0;p<4;p++){
                LDSM4(bhf[p][0],bhf[p][1],bhf[p][2],bhf[p][3], sb + boff[p] + kb);
                LDSM4(blf[p][0],blf[p][1],blf[p][2],blf[p][3], sb + A1 + boff[p] + kb);
            }
            #pragma unroll
            for (int p=0;p<4;p++){
                mma3b(acc[0][2*p  ], ah0, al0, bhf[p][0], bhf[p][1], blf[p][0], blf[p][1]);
                mma3b(acc[1][2*p  ], ah1, al1, bhf[p][0], bhf[p][1], blf[p][0], blf[p][1]);
                mma3b(acc[0][2*p+1], ah0, al0, bhf[p][2], bhf[p][3], blf[p][2], blf[p][3]);
                mma3b(acc[1][2*p+1], ah1, al1, bhf[p][2], bhf[p][3], blf[p][2], blf[p][3]);
            }
        }
        __syncthreads();
        // transpose-stage out[t][s] -> sW[s][t]
        #pragma unroll
        for (int mi=0; mi<2; mi++){
            #pragma unroll
            for (int ni=0; ni<8; ni++){
                int r = wm + mi*16 + g;
                int c = wn + ni*8 + tg*2;
                sW[c*132 + r]       = acc[mi][ni][0];
                sW[(c+1)*132 + r]   = acc[mi][ni][1];
                sW[c*132 + r+8]     = acc[mi][ni][2];
                sW[(c+1)*132 + r+8] = acc[mi][ni][3];
            }
        }
    }
    __syncthreads();

    // AT[b*128+s][h*128+t] as bf16 hi/lo
    const int h = bid & 31, b = bid >> 5;
    __nv_bfloat16* oh = g_AThi + (size_t)(b*128)*CC + h*128;
    __nv_bfloat16* ol = g_ATlo + (size_t)(b*128)*CC + h*128;
    #pragma unroll
    for (int i=0;i<16;i++){
        int idx = tid + i*256;
        int sc = idx>>5, t4 = (idx&31)*4;
        float4 v = *(const float4*)&sW[sc*132 + t4];
        uint32_t h0,l0,h1,l1;
        split2(v.x, v.y, h0, l0);
        split2(v.z, v.w, h1, l1);
        uint2 hv; hv.x=h0; hv.y=h1;
        uint2 lv; lv.x=l0; lv.y=l1;
        *(uint2*)(oh + (size_t)sc*CC + t4) = hv;
        *(uint2*)(ol + (size_t)sc*CC + t4) = lv;
    }
}

extern "C" void kernel_launch(void* const* d_in, const int* in_sizes, int n_in,
                              void* d_out, int out_size)
{
    const float* x  = (const float*)d_in[0];
    const float* wq = (const float*)d_in[1];
    const float* wk = (const float*)d_in[2];
    const float* wv = (const float*)d_in[3];
    const float* wp = (const float*)d_in[4];
    const float* bp = (const float*)d_in[5];
    float* out = (float*)d_out;

    const int smemG = (256 + NSTG*STGU + 128*132)*4;   // 216064 B
    const int smemA = (4*AARR + 128*132)*4;            // 206848 B
    cudaFuncSetAttribute(gemm_bf<0>, cudaFuncAttributeMaxDynamicSharedMemorySize, smemG);
    cudaFuncSetAttribute(gemm_bf<1>, cudaFuncAttributeMaxDynamicSharedMemorySize, smemG);
    cudaFuncSetAttribute(attn_kernel, cudaFuncAttributeMaxDynamicSharedMemorySize, smemA);

    conv_flat<0><<<16384, 256>>>(x);                       // x -> Xhi/Xlo
    conv_wT<<<dim3(4,128,96), dim3(32,8)>>>(wq, wk, wv);   // w -> Whi/Wlo (transposed)
    conv_flat<1><<<8192, 256>>>(wp);                       // wp -> Phi/Plo
    gemm_bf<0><<<148, 384, smemG>>>(nullptr, nullptr);     // QKV persistent
    attn_kernel<<<2048, 256, smemA>>>();                   // attention -> AThi/ATlo
    gemm_bf<1><<<148, 384, smemG>>>(bp, out);              // proj persistent
}

// round 16
// speedup vs baseline: 1.0054x; 1.0054x over previous
#include <cuda_runtime.h>
#include <cuda_bf16.h>
#include <cstdint>
#include <cstring>

#define BB 64
#define TT 128
#define CC 4096
#define HH 32
#define HSD 128
__device__ const float SCALE = 0.17677669529663687f;

// device-global scratch
__device__ __nv_bfloat16 g_Xhi[(size_t)8192*4096];
__device__ __nv_bfloat16 g_Xlo[(size_t)8192*4096];
__device__ __nv_bfloat16 g_Whi[(size_t)3*4096*4096];
__device__ __nv_bfloat16 g_Wlo[(size_t)3*4096*4096];
__device__ __nv_bfloat16 g_Phi[(size_t)4096*4096];
__device__ __nv_bfloat16 g_Plo[(size_t)4096*4096];
__device__ __nv_bfloat16 g_AThi[(size_t)8192*4096];
__device__ __nv_bfloat16 g_ATlo[(size_t)8192*4096];
__device__ __nv_bfloat16 g_Qhi[(size_t)BB*HH*TT*HSD];
__device__ __nv_bfloat16 g_Qlo[(size_t)BB*HH*TT*HSD];
__device__ __nv_bfloat16 g_Khi[(size_t)BB*HH*TT*HSD];
__device__ __nv_bfloat16 g_Klo[(size_t)BB*HH*TT*HSD];
__device__ __nv_bfloat16 g_VThi[(size_t)BB*HH*TT*HSD];   // [b,h][s][t]
__device__ __nv_bfloat16 g_VTlo[(size_t)BB*HH*TT*HSD];

__device__ __forceinline__ uint32_t smem_u32(const void* p){
    uint32_t a;
    asm("{ .reg .u64 t; cvta.to.shared.u64 t, %1; cvt.u32.u64 %0, t; }" : "=r"(a) : "l"(p));
    return a;
}
__device__ __forceinline__ void cp16g(const void* smem_dst, const void* gsrc){
    uint32_t s = (uint32_t)__cvta_generic_to_shared(smem_dst);
    asm volatile("cp.async.cg.shared.global [%0], [%1], 16;" :: "r"(s), "l"(gsrc));
}
#define CP_COMMIT() asm volatile("cp.async.commit_group;")
#define CP_WAIT0()  asm volatile("cp.async.wait_group 0;")
#define MBAR_INIT(a, c) \
    asm volatile("mbarrier.init.shared.b64 [%0], %1;" :: "r"(a), "r"(c) : "memory")
#define MBAR_ARRIVE(a) \
    asm volatile("mbarrier.arrive.shared.b64 _, [%0];" :: "r"(a) : "memory")
#define CPA_ARRIVE(a) \
    asm volatile("cp.async.mbarrier.arrive.noinc.shared::cta.b64 [%0];" :: "r"(a) : "memory")
#define MBAR_WAIT(a, ph) do{ unsigned _d=0; while(!_d){ \
    asm volatile("{\n\t.reg .pred p;\n\t" \
        "mbarrier.try_wait.parity.acquire.cta.shared::cta.b64 p, [%1], %2;\n\t" \
        "selp.b32 %0, 1, 0, p;\n\t}" : "=r"(_d) : "r"(a), "r"(ph) : "memory"); } }while(0)
#define BARC(id, n) asm volatile("bar.sync %0, %1;" :: "r"(id), "r"(n) : "memory")

#define LDSM4(r0,r1,r2,r3, addr) \
    asm volatile("ldmatrix.sync.aligned.m8n8.x4.shared.b16 {%0,%1,%2,%3}, [%4];" \
        : "=r"(r0), "=r"(r1), "=r"(r2), "=r"(r3) : "r"(addr))

// bf16 m16n8k16 MMA
__device__ __forceinline__ void mma_bf16(float* d, const uint32_t* a, uint32_t b0, uint32_t b1){
    asm volatile("mma.sync.aligned.m16n8k16.row.col.f32.bf16.bf16.f32 "
        "{%0,%1,%2,%3},{%4,%5,%6,%7},{%8,%9},{%0,%1,%2,%3};"
        : "+f"(d[0]), "+f"(d[1]), "+f"(d[2]), "+f"(d[3])
        : "r"(a[0]), "r"(a[1]), "r"(a[2]), "r"(a[3]), "r"(b0), "r"(b1));
}
__device__ __forceinline__ void mma3b(float* d, const uint32_t* ah, const uint32_t* al,
                                      uint32_t bh0, uint32_t bh1, uint32_t bl0, uint32_t bl1){
    mma_bf16(d, al, bh0, bh1);
    mma_bf16(d, ah, bl0, bl1);
    mma_bf16(d, ah, bh0, bh1);
}

__device__ __forceinline__ uint32_t pack2(float a, float b){
    __nv_bfloat162 t(__float2bfloat16(a), __float2bfloat16(b));  // x=low, y=high
    uint32_t u; memcpy(&u, &t, 4); return u;
}
__device__ __forceinline__ void split2(float a, float b, uint32_t& hi, uint32_t& lo){
    __nv_bfloat16 h0 = __float2bfloat16(a), h1 = __float2bfloat16(b);
    hi = pack2(a, b);
    lo = pack2(a - __bfloat162float(h0), b - __bfloat162float(h1));
}

// -------- prep: flat fp32 -> bf16 hi/lo.  0: x -> X   1: wp -> P --------
template<int MODE>
__global__ __launch_bounds__(256)
void conv_flat(const float* __restrict__ src)
{
    size_t i = (size_t)blockIdx.x * 256 + threadIdx.x;
    const float4* s4 = (const float4*)src;
    float4 a = s4[2*i], b = s4[2*i+1];
    float v[8] = {a.x,a.y,a.z,a.w,b.x,b.y,b.z,b.w};
    alignas(16) __nv_bfloat16 h[8], l[8];
    #pragma unroll
    for (int j=0;j<8;j++){
        h[j] = __float2bfloat16(v[j]);
        l[j] = __float2bfloat16(v[j] - __bfloat162float(h[j]));
    }
    __nv_bfloat16* dh = (MODE==0) ? g_Xhi : g_Phi;
    __nv_bfloat16* dl = (MODE==0) ? g_Xlo : g_Plo;
    ((uint4*)dh)[i] = *(const uint4*)h;
    ((uint4*)dl)[i] = *(const uint4*)l;
}

// -------- prep: w[h][c][s] -> W[z][n=h*128+s][k=c] transpose-split --------
__global__ __launch_bounds__(256)
void conv_wT(const float* __restrict__ wq, const float* __restrict__ wk,
             const float* __restrict__ wv)
{
    __shared__ float tile[32][33];
    const int st = blockIdx.x, ct = blockIdx.y;
    const int z = blockIdx.z >> 5, h = blockIdx.z & 31;
    const float* w = (z==0 ? wq : (z==1 ? wk : wv)) + (size_t)h*CC*HSD;
    const int tx = threadIdx.x, ty = threadIdx.y;
    #pragma unroll
    for (int j=0;j<4;j++)
        tile[ty+8*j][tx] = w[(size_t)(ct*32 + ty+8*j)*HSD + st*32 + tx];
    __syncthreads();
    __nv_bfloat16* oh = g_Whi + (size_t)z*CC*CC;
    __nv_bfloat16* ol = g_Wlo + (size_t)z*CC*CC;
    #pragma unroll
    for (int j=0;j<4;j++){
        int sI = st*32 + ty+8*j, c = ct*32 + tx;
        float v = tile[tx][ty+8*j];
        __nv_bfloat16 hv = __float2bfloat16(v);
        __nv_bfloat16 lv = __float2bfloat16(v - __bfloat162float(hv));
        size_t o = (size_t)(h*128 + sI)*CC + c;
        oh[o] = hv; ol[o] = lv;
    }
}

// ---------------------------------------------------------------------------
// Warp-specialized bf16 3-term GEMM, ldmatrix fragments.
// CTA 128x128, K-tile 64, 3 mbarrier stages, 384 threads.
// EMPTY barriers use elected per-warp arrives (count 8).
// MODE 0: X @ W[z] -> Qhi/lo, Khi/lo (bf16) or VT hi/lo (transposed bf16)
// MODE 1: AT @ P + bias -> Cout (f32)
// ---------------------------------------------------------------------------
#define PITCH 36
#define ARRW  (128*PITCH)
#define NSTG  3
#define STGU  (4*ARRW)
#define FULLB(s)  (sb + 16*(s))
#define EMPTYB(s) (sb + 16*(s) + 8)

template<int MODE>
__global__ __launch_bounds__(384, 1)
void gemm_bf(const float* __restrict__ bias, float* __restrict__ Cout)
{
    extern __shared__ uint32_t sm[];
    const uint32_t sb = smem_u32(sm);
    const int tid = threadIdx.x;
    const int lid = blockIdx.x;
    const int pid = lid >> 8, rem = lid & 255;
    const int mt = pid*8 + (rem & 7), nt = rem >> 3;
    const int m0 = mt*128, n0 = nt*128;
    const int z = (MODE==0) ? blockIdx.z : 0;

    const __nv_bfloat16 *Ah, *Al, *Bh, *Bl;
    if (MODE==0){ Ah=g_Xhi; Al=g_Xlo; Bh=g_Whi+(size_t)z*CC*CC; Bl=g_Wlo+(size_t)z*CC*CC; }
    else        { Ah=g_AThi; Al=g_ATlo; Bh=g_Phi; Bl=g_Plo; }

    if (tid==0){
        #pragma unroll
        for (int s=0;s<NSTG;s++){ MBAR_INIT(FULLB(s), 128); MBAR_INIT(EMPTYB(s), 8); }
    }
    __syncthreads();

    const int NK = CC/64;

    if (tid >= 256){
        // ---------------- producers (128 threads) ----------------
        const int pt = tid - 256;
        int ph[NSTG] = {1,1,1};
        int s = 0;
        for (int kt=0; kt<NK; kt++){
            MBAR_WAIT(EMPTYB(s), ph[s]); ph[s] ^= 1;
            uint32_t* base = sm + 256 + s*STGU;
            const size_t kO = (size_t)kt*64;
            #pragma unroll
            for (int j=0;j<32;j++){
                int id = pt + j*128;
                int arr = id >> 10;
                int c   = id & 1023;
                int row = c >> 3, c16 = c & 7;
                uint32_t* dst = base + arr*ARRW + row*PITCH + c16*4;
                const __nv_bfloat16* gp =
                    (arr==0) ? Ah + (size_t)(m0+row)*CC + kO + c16*8 :
                    (arr==1) ? Al + (size_t)(m0+row)*CC + kO + c16*8 :
                    (arr==2) ? Bh + (size_t)(n0+row)*CC + kO + c16*8 :
                               Bl + (size_t)(n0+row)*CC + kO + c16*8;
                cp16g(dst, gp);
            }
            CPA_ARRIVE(FULLB(s));
            s = (s==NSTG-1) ? 0 : s+1;
        }
        return;
    }

    // ---------------- consumers (256 threads, 8 warps) ----------------
    const int warp = tid>>5, lane = tid&31, g = lane>>2, tg = lane&3;
    const int wm = (warp>>1)*32, wn = (warp&1)*64;

    const int lr = lane & 15;
    const int lc = lane >> 4;
    const int bn = (lane & 7) + ((lane & 16) ? 8 : 0);
    const int bc = (lane >> 3) & 1;
    const uint32_t aoff0 = (uint32_t)(((wm      + lr)*PITCH + lc*4)*4);
    const uint32_t aoff1 = (uint32_t)(((wm + 16 + lr)*PITCH + lc*4)*4);
    uint32_t boff[4];
    #pragma unroll
    for (int p=0;p<4;p++) boff[p] = (uint32_t)(((wn + p*16 + bn)*PITCH + bc*4)*4);
    const uint32_t dbase = sb + 1024;
    const uint32_t A4 = ARRW*4;

    float acc[2][8][4];
    #pragma unroll
    for (int a=0;a<2;a++)
        #pragma unroll
        for (int b=0;b<8;b++)
            #pragma unroll
            for (int c=0;c<4;c++) acc[a][b][c] = 0.f;

    int phf[NSTG] = {0,0,0};
    int s = 0;
    for (int kt=0; kt<NK; kt++){
        MBAR_WAIT(FULLB(s), phf[s]); phf[s] ^= 1;
        const uint32_t stgb = dbase + s*(STGU*4);
        #pragma unroll
        for (int kk=0; kk<4; kk++){
            const uint32_t kb = kk*32;
            uint32_t ah0[4], ah1[4], al0[4], al1[4];
            LDSM4(ah0[0],ah0[1],ah0[2],ah0[3], stgb + aoff0 + kb);
            LDSM4(ah1[0],ah1[1],ah1[2],ah1[3], stgb + aoff1 + kb);
            LDSM4(al0[0],al0[1],al0[2],al0[3], stgb + A4 + aoff0 + kb);
            LDSM4(al1[0],al1[1],al1[2],al1[3], stgb + A4 + aoff1 + kb);
            uint32_t bh[4][4], bl[4][4];
            #pragma unroll
            for (int p=0;p<4;p++){
                LDSM4(bh[p][0],bh[p][1],bh[p][2],bh[p][3], stgb + 2*A4 + boff[p] + kb);
                LDSM4(bl[p][0],bl[p][1],bl[p][2],bl[p][3], stgb + 3*A4 + boff[p] + kb);
            }
            if (kk==3 && lane==0) MBAR_ARRIVE(EMPTYB(s));  // elected per-warp arrive
            #pragma unroll
            for (int p=0;p<4;p++){
                mma3b(acc[0][2*p  ], ah0, al0, bh[p][0], bh[p][1], bl[p][0], bl[p][1]);
                mma3b(acc[1][2*p  ], ah1, al1, bh[p][0], bh[p][1], bl[p][0], bl[p][1]);
                mma3b(acc[0][2*p+1], ah0, al0, bh[p][2], bh[p][3], bl[p][2], bl[p][3]);
                mma3b(acc[1][2*p+1], ah1, al1, bh[p][2], bh[p][3], bl[p][2], bl[p][3]);
            }
        }
        s = (s==NSTG-1) ? 0 : s+1;
    }

    if (MODE==0){
        const int b = m0 >> 7;          // batch
        const int head = nt;
        if (z < 2){
            __nv_bfloat16* dh = (z==0) ? g_Qhi : g_Khi;
            __nv_bfloat16* dl = (z==0) ? g_Qlo : g_Klo;
            #pragma unroll
            for (int mi=0; mi<2; mi++){
                #pragma unroll
                for (int ni=0; ni<8; ni++){
                    int t = (wm + mi*16 + g);
                    int sc = wn + ni*8 + tg*2;
                    size_t idx = (((size_t)(b*HH + head))*TT + t)*HSD + sc;
                    uint32_t h0, l0, h1, l1;
                    split2(acc[mi][ni][0], acc[mi][ni][1], h0, l0);
                    split2(acc[mi][ni][2], acc[mi][ni][3], h1, l1);
                    *(uint32_t*)(dh + idx) = h0;
                    *(uint32_t*)(dl + idx) = l0;
                    *(uint32_t*)(dh + idx + 8*HSD) = h1;
                    *(uint32_t*)(dl + idx + 8*HSD) = l1;
                }
            }
        } else {
            // V: transpose through smem (consumers-only barrier), write [s][t]
            float* sT = (float*)(sm + 256);
            BARC(1, 256);   // all consumers done reading stage smem
            #pragma unroll
            for (int mi=0; mi<2; mi++){
                #pragma unroll
                for (int ni=0; ni<8; ni++){
                    int t = wm + mi*16 + g;
                    int sc = wn + ni*8 + tg*2;
                    // store TRANSPOSED: row = s, col = t
                    sT[sc*132 + t]       = acc[mi][ni][0];
                    sT[(sc+1)*132 + t]   = acc[mi][ni][1];
                    sT[sc*132 + t+8]     = acc[mi][ni][2];
                    sT[(sc+1)*132 + t+8] = acc[mi][ni][3];
                }
            }
            BARC(1, 256);
            __nv_bfloat16* vh = g_VThi + (((size_t)(b*HH + head))*HSD)*TT;
            __nv_bfloat16* vl = g_VTlo + (((size_t)(b*HH + head))*HSD)*TT;
            #pragma unroll
            for (int i=0;i<16;i++){
                int idx = tid + i*256;
                int sc = idx>>5, t4 = (idx&31)*4;
                float4 v = *(const float4*)&sT[sc*132 + t4];
                uint32_t h0,l0,h1,l1;
                split2(v.x, v.y, h0, l0);
                split2(v.z, v.w, h1, l1);
                uint2 hv; hv.x = h0; hv.y = h1;
                uint2 lv; lv.x = l0; lv.y = l1;
                *(uint2*)(vh + (size_t)sc*TT + t4) = hv;
                *(uint2*)(vl + (size_t)sc*TT + t4) = lv;
            }
        }
    } else {
        #pragma unroll
        for (int mi=0; mi<2; mi++){
            #pragma unroll
            for (int ni=0; ni<8; ni++){
                int mrow = m0 + wm + mi*16 + g;
                int ncol = n0 + wn + ni*8 + tg*2;
                float bv0 = bias[ncol], bv1 = bias[ncol+1];
                float* p = Cout + (size_t)mrow*CC + ncol;
                p[0] = acc[mi][ni][0] + bv0; p[1] = acc[mi][ni][1] + bv1;
                p[8*CC] = acc[mi][ni][2] + bv0; p[8*CC+1] = acc[mi][ni][3] + bv1;
            }
        }
    }
}

// ---------------------------------------------------------------------------
// Attention, all-bf16 3-term: QK^T -> softmax over QUERY axis -> P@V.
// ---------------------------------------------------------------------------
#define APITCH 68
#define AARR   (128*APITCH)
__global__ __launch_bounds__(256)
void attn_kernel()
{
    extern __shared__ uint32_t smu[];
    const uint32_t sb = smem_u32(smu);
    float* sW = (float*)(smu + 4*AARR);     // [t][132]

    const int tid = threadIdx.x;
    const int bid = blockIdx.x;
    const int bh = bid;
    const __nv_bfloat16* qh = g_Qhi + (size_t)bh*TT*HSD;
    const __nv_bfloat16* ql = g_Qlo + (size_t)bh*TT*HSD;
    const __nv_bfloat16* kh = g_Khi + (size_t)bh*TT*HSD;
    const __nv_bfloat16* kl = g_Klo + (size_t)bh*TT*HSD;

    #pragma unroll
    for (int i=0;i<32;i++){
        int idx = tid + i*256;
        int arr = idx >> 11;
        int c   = idx & 2047;
        int row = c >> 4, ch = c & 15;
        uint32_t* dst = smu + arr*AARR + row*APITCH + ch*4;
        const __nv_bfloat16* gp =
            (arr==0) ? qh + (size_t)row*HSD + ch*8 :
            (arr==1) ? ql + (size_t)row*HSD + ch*8 :
            (arr==2) ? kh + (size_t)row*HSD + ch*8 :
                       kl + (size_t)row*HSD + ch*8;
        cp16g(dst, gp);
    }
    CP_COMMIT(); CP_WAIT0();
    __syncthreads();

    const int warp = tid>>5, lane = tid&31, g = lane>>2, tg = lane&3;
    const int wm = (warp>>1)*32, wn = (warp&1)*64;
    const int lr = lane & 15;
    const int lc = lane >> 4;
    const int bn = (lane & 7) + ((lane & 16) ? 8 : 0);
    const int bc = (lane >> 3) & 1;
    const uint32_t aoff0 = (uint32_t)(((wm      + lr)*APITCH + lc*4)*4);
    const uint32_t aoff1 = (uint32_t)(((wm + 16 + lr)*APITCH + lc*4)*4);
    uint32_t boff[4];
    #pragma unroll
    for (int p=0;p<4;p++) boff[p] = (uint32_t)(((wn + p*16 + bn)*APITCH + bc*4)*4);
    const uint32_t A1 = AARR*4;

    // ---- QK^T: A = Q (arrays 0,1), B = K (arrays 2,3) ----
    {
        float acc[2][8][4];
        #pragma unroll
        for (int a=0;a<2;a++)
            #pragma unroll
            for (int c2=0;c2<8;c2++)
                #pragma unroll
                for (int d2=0;d2<4;d2++) acc[a][c2][d2]=0.f;
        #pragma unroll
        for (int kk=0; kk<8; kk++){
            const uint32_t kb = kk*32;
            uint32_t ah0[4], ah1[4], al0[4], al1[4];
            LDSM4(ah0[0],ah0[1],ah0[2],ah0[3], sb + aoff0 + kb);
            LDSM4(ah1[0],ah1[1],ah1[2],ah1[3], sb + aoff1 + kb);
            LDSM4(al0[0],al0[1],al0[2],al0[3], sb + A1 + aoff0 + kb);
            LDSM4(al1[0],al1[1],al1[2],al1[3], sb + A1 + aoff1 + kb);
            uint32_t bhf[4][4], blf[4][4];
            #pragma unroll
            for (int p=0;p<4;p++){
                LDSM4(bhf[p][0],bhf[p][1],bhf[p][2],bhf[p][3], sb + 2*A1 + boff[p] + kb);
                LDSM4(blf[p][0],blf[p][1],blf[p][2],blf[p][3], sb + 3*A1 + boff[p] + kb);
            }
            #pragma unroll
            for (int p=0;p<4;p++){
                mma3b(acc[0][2*p  ], ah0, al0, bhf[p][0], bhf[p][1], blf[p][0], blf[p][1]);
                mma3b(acc[1][2*p  ], ah1, al1, bhf[p][0], bhf[p][1], blf[p][0], blf[p][1]);
                mma3b(acc[0][2*p+1], ah0, al0, bhf[p][2], bhf[p][3], blf[p][2], blf[p][3]);
                mma3b(acc[1][2*p+1], ah1, al1, bhf[p][2], bhf[p][3], blf[p][2], blf[p][3]);
            }
        }
        #pragma unroll
        for (int mi=0; mi<2; mi++){
            #pragma unroll
            for (int ni=0; ni<8; ni++){
                int r = wm + mi*16 + g;
                int c = wn + ni*8 + tg*2;
                sW[r*132+c]       = acc[mi][ni][0]*SCALE;
                sW[r*132+c+1]     = acc[mi][ni][1]*SCALE;
                sW[(r+8)*132+c]   = acc[mi][ni][2]*SCALE;
                sW[(r+8)*132+c+1] = acc[mi][ni][3]*SCALE;
            }
        }
    }
    __syncthreads();

    if (tid < 128){
        const int u = tid;
        float mx = -1e30f;
        for (int t=0;t<128;t++) mx = fmaxf(mx, sW[t*132+u]);
        float ssum = 0.f;
        for (int t=0;t<128;t++){ float e = __expf(sW[t*132+u]-mx); sW[t*132+u]=e; ssum+=e; }
        float inv = 1.f/ssum;
        for (int t=0;t<128;t++) sW[t*132+u] *= inv;
    } else {
        const int lt = tid - 128;
        const __nv_bfloat16* vh = g_VThi + (size_t)bh*HSD*TT;
        const __nv_bfloat16* vl = g_VTlo + (size_t)bh*HSD*TT;
        #pragma unroll
        for (int i=0;i<32;i++){
            int idx = lt + i*128;
            int arr = idx >> 11;
            int c   = idx & 2047;
            int row = c >> 4, ch = c & 15;
            uint32_t* dst = smu + arr*AARR + row*APITCH + ch*4;
            const __nv_bfloat16* gp = (arr==0)
                ? vh + (size_t)row*TT + ch*8
                : vl + (size_t)row*TT + ch*8;
            cp16g(dst, gp);
        }
        CP_COMMIT(); CP_WAIT0();
    }
    __syncthreads();

    // convert W f32 -> bf16 hi/lo into K region (arrays 2,3)
    {
        int r = tid >> 1, half = tid & 1;
        uint32_t* wh = smu + 2*AARR + r*APITCH + half*32;
        uint32_t* wl = smu + 3*AARR + r*APITCH + half*32;
        const float* src = sW + r*132 + half*64;
        #pragma unroll
        for (int j=0;j<32;j++){
            uint32_t hi, lo;
            split2(src[2*j], src[2*j+1], hi, lo);
            wh[j] = hi; wl[j] = lo;
        }
    }
    __syncthreads();

    // ---- P@V: A = W (arrays 2,3), B = V^T (arrays 0,1) ----
    {
        float acc[2][8][4];
        #pragma unroll
        for (int a=0;a<2;a++)
            #pragma unroll
            for (int c2=0;c2<8;c2++)
                #pragma unroll
                for (int d2=0;d2<4;d2++) acc[a][c2][d2]=0.f;
        #pragma unroll
        for (int kk=0; kk<8; kk++){
            const uint32_t kb = kk*32;
            uint32_t ah0[4], ah1[4], al0[4], al1[4];
            LDSM4(ah0[0],ah0[1],ah0[2],ah0[3], sb + 2*A1 + aoff0 + kb);
            LDSM4(ah1[0],ah1[1],ah1[2],ah1[3], sb + 2*A1 + aoff1 + kb);
            LDSM4(al0[0],al0[1],al0[2],al0[3], sb + 3*A1 + aoff0 + kb);
            LDSM4(al1[0],al1[1],al1[2],al1[3], sb + 3*A1 + aoff1 + kb);
            uint32_t bhf[4][4], blf[4][4];
            #pragma unroll
            for (int p=0;p<4;p++){
                LDSM4(bhf[p][0],bhf[p][1],bhf[p][2],bhf[p][3], sb + boff[p] + kb);
                LDSM4(blf[p][0],blf[p][1],blf[p][2],blf[p][3], sb + A1 + boff[p] + kb);
            }
            #pragma unroll
            for (int p=0;p<4;p++){
                mma3b(acc[0][2*p  ], ah0, al0, bhf[p][0], bhf[p][1], blf[p][0], blf[p][1]);
                mma3b(acc[1][2*p  ], ah1, al1, bhf[p][0], bhf[p][1], blf[p][0], blf[p][1]);
                mma3b(acc[0][2*p+1], ah0, al0, bhf[p][2], bhf[p][3], blf[p][2], blf[p][3]);
                mma3b(acc[1][2*p+1], ah1, al1, bhf[p][2], bhf[p][3], blf[p][2], blf[p][3]);
            }
        }
        __syncthreads();
        // transpose-stage out[t][s] -> sW[s][t]
        #pragma unroll
        for (int mi=0; mi<2; mi++){
            #pragma unroll
            for (int ni=0; ni<8; ni++){
                int r = wm + mi*16 + g;
                int c = wn + ni*8 + tg*2;
                sW[c*132 + r]       = acc[mi][ni][0];
                sW[(c+1)*132 + r]   = acc[mi][ni][1];
                sW[c*132 + r+8]     = acc[mi][ni][2];
                sW[(c+1)*132 + r+8] = acc[mi][ni][3];
            }
        }
    }
    __syncthreads();

    // AT[b*128+s][h*128+t] as bf16 hi/lo
    const int h = bid & 31, b = bid >> 5;
    __nv_bfloat16* oh = g_AThi + (size_t)(b*128)*CC + h*128;
    __nv_bfloat16* ol = g_ATlo + (size_t)(b*128)*CC + h*128;
    #pragma unroll
    for (int i=0;i<16;i++){
        int idx = tid + i*256;
        int sc = idx>>5, t4 = (idx&31)*4;
        float4 v = *(const float4*)&sW[sc*132 + t4];
        uint32_t h0,l0,h1,l1;
        split2(v.x, v.y, h0, l0);
        split2(v.z, v.w, h1, l1);
        uint2 hv; hv.x=h0; hv.y=h1;
        uint2 lv; lv.x=l0; lv.y=l1;
        *(uint2*)(oh + (size_t)sc*CC + t4) = hv;
        *(uint2*)(ol + (size_t)sc*CC + t4) = lv;
    }
}

extern "C" void kernel_launch(void* const* d_in, const int* in_sizes, int n_in,
                              void* d_out, int out_size)
{
    const float* x  = (const float*)d_in[0];
    const float* wq = (const float*)d_in[1];
    const float* wk = (const float*)d_in[2];
    const float* wv = (const float*)d_in[3];
    const float* wp = (const float*)d_in[4];
    const float* bp = (const float*)d_in[5];
    float* out = (float*)d_out;

    const int smemG = (256 + NSTG*STGU)*4;          // 222208 B
    const int smemA = (4*AARR + 128*132)*4;         // 206848 B
    cudaFuncSetAttribute(gemm_bf<0>, cudaFuncAttributeMaxDynamicSharedMemorySize, smemG);
    cudaFuncSetAttribute(gemm_bf<1>, cudaFuncAttributeMaxDynamicSharedMemorySize, smemG);
    cudaFuncSetAttribute(attn_kernel, cudaFuncAttributeMaxDynamicSharedMemorySize, smemA);

    conv_flat<0><<<16384, 256>>>(x);                       // x -> Xhi/Xlo
    conv_wT<<<dim3(4,128,96), dim3(32,8)>>>(wq, wk, wv);   // w -> Whi/Wlo (transposed)
    conv_flat<1><<<8192, 256>>>(wp);                       // wp -> Phi/Plo
    gemm_bf<0><<<dim3(2048,1,3), 384, smemG>>>(nullptr, nullptr);  // QKV (bf16 out, V transposed)
    attn_kernel<<<2048, 256, smemA>>>();                   // attention -> AThi/ATlo
    gemm_bf<1><<<dim3(2048,1,1), 384, smemG>>>(bp, out);   // proj
}

// round 17
// speedup vs baseline: 1.0289x; 1.0234x over previous
#include <cuda_runtime.h>
#include <cuda_bf16.h>
#include <cstdint>
#include <cstring>

#define BB 64
#define TT 128
#define CC 4096
#define HH 32
#define HSD 128
__device__ const float SCALE = 0.17677669529663687f;

// device-global scratch
__device__ __nv_bfloat16 g_Xhi[(size_t)8192*4096];
__device__ __nv_bfloat16 g_Xlo[(size_t)8192*4096];
__device__ __nv_bfloat16 g_Whi[(size_t)3*4096*4096];
__device__ __nv_bfloat16 g_Wlo[(size_t)3*4096*4096];
__device__ __nv_bfloat16 g_Qhi[(size_t)BB*HH*TT*HSD];
__device__ __nv_bfloat16 g_Qlo[(size_t)BB*HH*TT*HSD];
__device__ __nv_bfloat16 g_Khi[(size_t)BB*HH*TT*HSD];
__device__ __nv_bfloat16 g_Klo[(size_t)BB*HH*TT*HSD];
__device__ __nv_bfloat16 g_VThi[(size_t)BB*HH*TT*HSD];   // [b,h][s][t]
__device__ __nv_bfloat16 g_VTlo[(size_t)BB*HH*TT*HSD];
__device__ uint32_t g_att[(size_t)8192*4096];            // att^T, tf32-rounded f32 bits
__device__ uint32_t g_Ptf[(size_t)4096*4096];            // wp, tf32-rounded f32 bits

__device__ __forceinline__ uint32_t smem_u32(const void* p){
    uint32_t a;
    asm("{ .reg .u64 t; cvta.to.shared.u64 t, %1; cvt.u32.u64 %0, t; }" : "=r"(a) : "l"(p));
    return a;
}
__device__ __forceinline__ void cp16g(const void* smem_dst, const void* gsrc){
    uint32_t s = (uint32_t)__cvta_generic_to_shared(smem_dst);
    asm volatile("cp.async.cg.shared.global [%0], [%1], 16;" :: "r"(s), "l"(gsrc));
}
#define CP_COMMIT() asm volatile("cp.async.commit_group;")
#define CP_WAIT0()  asm volatile("cp.async.wait_group 0;")
#define MBAR_INIT(a, c) \
    asm volatile("mbarrier.init.shared.b64 [%0], %1;" :: "r"(a), "r"(c) : "memory")
#define MBAR_ARRIVE(a) \
    asm volatile("mbarrier.arrive.shared.b64 _, [%0];" :: "r"(a) : "memory")
#define CPA_ARRIVE(a) \
    asm volatile("cp.async.mbarrier.arrive.noinc.shared::cta.b64 [%0];" :: "r"(a) : "memory")
#define MBAR_WAIT(a, ph) do{ unsigned _d=0; while(!_d){ \
    asm volatile("{\n\t.reg .pred p;\n\t" \
        "mbarrier.try_wait.parity.acquire.cta.shared::cta.b64 p, [%1], %2;\n\t" \
        "selp.b32 %0, 1, 0, p;\n\t}" : "=r"(_d) : "r"(a), "r"(ph) : "memory"); } }while(0)
#define BARC(id, n) asm volatile("bar.sync %0, %1;" :: "r"(id), "r"(n) : "memory")

#define LDSM4(r0,r1,r2,r3, addr) \
    asm volatile("ldmatrix.sync.aligned.m8n8.x4.shared.b16 {%0,%1,%2,%3}, [%4];" \
        : "=r"(r0), "=r"(r1), "=r"(r2), "=r"(r3) : "r"(addr))

// bf16 m16n8k16 MMA
__device__ __forceinline__ void mma_bf16(float* d, const uint32_t* a, uint32_t b0, uint32_t b1){
    asm volatile("mma.sync.aligned.m16n8k16.row.col.f32.bf16.bf16.f32 "
        "{%0,%1,%2,%3},{%4,%5,%6,%7},{%8,%9},{%0,%1,%2,%3};"
        : "+f"(d[0]), "+f"(d[1]), "+f"(d[2]), "+f"(d[3])
        : "r"(a[0]), "r"(a[1]), "r"(a[2]), "r"(a[3]), "r"(b0), "r"(b1));
}
__device__ __forceinline__ void mma3b(float* d, const uint32_t* ah, const uint32_t* al,
                                      uint32_t bh0, uint32_t bh1, uint32_t bl0, uint32_t bl1){
    mma_bf16(d, al, bh0, bh1);
    mma_bf16(d, ah, bl0, bl1);
    mma_bf16(d, ah, bh0, bh1);
}
// tf32 m16n8k8 MMA (operands pre-rounded tf32)
__device__ __forceinline__ void mma_tf32(float* d, const uint32_t* a, uint32_t b0, uint32_t b1){
    asm volatile("mma.sync.aligned.m16n8k8.row.col.f32.tf32.tf32.f32 "
        "{%0,%1,%2,%3},{%4,%5,%6,%7},{%8,%9},{%0,%1,%2,%3};"
        : "+f"(d[0]), "+f"(d[1]), "+f"(d[2]), "+f"(d[3])
        : "r"(a[0]), "r"(a[1]), "r"(a[2]), "r"(a[3]), "r"(b0), "r"(b1));
}
__device__ __forceinline__ uint32_t f2tf32(float f){
    uint32_t u; asm("cvt.rna.tf32.f32 %0, %1;" : "=r"(u) : "f"(f)); return u;
}

__device__ __forceinline__ uint32_t pack2(float a, float b){
    __nv_bfloat162 t(__float2bfloat16(a), __float2bfloat16(b));  // x=low, y=high
    uint32_t u; memcpy(&u, &t, 4); return u;
}
__device__ __forceinline__ void split2(float a, float b, uint32_t& hi, uint32_t& lo){
    __nv_bfloat16 h0 = __float2bfloat16(a), h1 = __float2bfloat16(b);
    hi = pack2(a, b);
    lo = pack2(a - __bfloat162float(h0), b - __bfloat162float(h1));
}

// -------- prep: x -> Xhi/Xlo (bf16 hi/lo) --------
__global__ __launch_bounds__(256)
void conv_x(const float* __restrict__ src)
{
    size_t i = (size_t)blockIdx.x * 256 + threadIdx.x;
    const float4* s4 = (const float4*)src;
    float4 a = s4[2*i], b = s4[2*i+1];
    float v[8] = {a.x,a.y,a.z,a.w,b.x,b.y,b.z,b.w};
    alignas(16) __nv_bfloat16 h[8], l[8];
    #pragma unroll
    for (int j=0;j<8;j++){
        h[j] = __float2bfloat16(v[j]);
        l[j] = __float2bfloat16(v[j] - __bfloat162float(h[j]));
    }
    ((uint4*)g_Xhi)[i] = *(const uint4*)h;
    ((uint4*)g_Xlo)[i] = *(const uint4*)l;
}

// -------- prep: wp -> g_Ptf (tf32-rounded f32 bits) --------
__global__ __launch_bounds__(256)
void conv_tf(const float* __restrict__ src)
{
    size_t i = (size_t)blockIdx.x * 256 + threadIdx.x;
    const float4* s4 = (const float4*)src;
    float4 a = s4[2*i], b = s4[2*i+1];
    float v[8] = {a.x,a.y,a.z,a.w,b.x,b.y,b.z,b.w};
    uint32_t o[8];
    #pragma unroll
    for (int j=0;j<8;j++) o[j] = f2tf32(v[j]);
    uint4 u0; u0.x=o[0]; u0.y=o[1]; u0.z=o[2]; u0.w=o[3];
    uint4 u1; u1.x=o[4]; u1.y=o[5]; u1.z=o[6]; u1.w=o[7];
    ((uint4*)g_Ptf)[2*i]   = u0;
    ((uint4*)g_Ptf)[2*i+1] = u1;
}

// -------- prep: w[h][c][s] -> W[z][n=h*128+s][k=c] transpose-split --------
__global__ __launch_bounds__(256)
void conv_wT(const float* __restrict__ wq, const float* __restrict__ wk,
             const float* __restrict__ wv)
{
    __shared__ float tile[32][33];
    const int st = blockIdx.x, ct = blockIdx.y;
    const int z = blockIdx.z >> 5, h = blockIdx.z & 31;
    const float* w = (z==0 ? wq : (z==1 ? wk : wv)) + (size_t)h*CC*HSD;
    const int tx = threadIdx.x, ty = threadIdx.y;
    #pragma unroll
    for (int j=0;j<4;j++)
        tile[ty+8*j][tx] = w[(size_t)(ct*32 + ty+8*j)*HSD + st*32 + tx];
    __syncthreads();
    __nv_bfloat16* oh = g_Whi + (size_t)z*CC*CC;
    __nv_bfloat16* ol = g_Wlo + (size_t)z*CC*CC;
    #pragma unroll
    for (int j=0;j<4;j++){
        int sI = st*32 + ty+8*j, c = ct*32 + tx;
        float v = tile[tx][ty+8*j];
        __nv_bfloat16 hv = __float2bfloat16(v);
        __nv_bfloat16 lv = __float2bfloat16(v - __bfloat162float(hv));
        size_t o = (size_t)(h*128 + sI)*CC + c;
        oh[o] = hv; ol[o] = lv;
    }
}

// ---------------------------------------------------------------------------
// QKV: warp-specialized bf16 3-term GEMM, ldmatrix fragments.
// CTA 128x128, K-tile 64, 3 mbarrier stages, 384 threads, early FULL wait.
// ---------------------------------------------------------------------------
#define PITCH 36
#define ARRW  (128*PITCH)
#define NSTG  3
#define STGU  (4*ARRW)
#define FULLB(s)  (sb + 16*(s))
#define EMPTYB(s) (sb + 16*(s) + 8)

__global__ __launch_bounds__(384, 1)
void gemm_bf(void)
{
    extern __shared__ uint32_t sm[];
    const uint32_t sb = smem_u32(sm);
    const int tid = threadIdx.x;
    const int lid = blockIdx.x;
    const int pid = lid >> 8, rem = lid & 255;
    const int mt = pid*8 + (rem & 7), nt = rem >> 3;
    const int m0 = mt*128, n0 = nt*128;
    const int z = blockIdx.z;

    const __nv_bfloat16 *Ah = g_Xhi, *Al = g_Xlo;
    const __nv_bfloat16 *Bh = g_Whi + (size_t)z*CC*CC, *Bl = g_Wlo + (size_t)z*CC*CC;

    if (tid==0){
        #pragma unroll
        for (int s=0;s<NSTG;s++){ MBAR_INIT(FULLB(s), 128); MBAR_INIT(EMPTYB(s), 256); }
    }
    __syncthreads();

    const int NK = CC/64;

    if (tid >= 256){
        const int pt = tid - 256;
        int ph[NSTG] = {1,1,1};
        int s = 0;
        for (int kt=0; kt<NK; kt++){
            MBAR_WAIT(EMPTYB(s), ph[s]); ph[s] ^= 1;
            uint32_t* base = sm + 256 + s*STGU;
            const size_t kO = (size_t)kt*64;
            #pragma unroll
            for (int j=0;j<32;j++){
                int id = pt + j*128;
                int arr = id >> 10;
                int c   = id & 1023;
                int row = c >> 3, c16 = c & 7;
                uint32_t* dst = base + arr*ARRW + row*PITCH + c16*4;
                const __nv_bfloat16* gp =
                    (arr==0) ? Ah + (size_t)(m0+row)*CC + kO + c16*8 :
                    (arr==1) ? Al + (size_t)(m0+row)*CC + kO + c16*8 :
                    (arr==2) ? Bh + (size_t)(n0+row)*CC + kO + c16*8 :
                               Bl + (size_t)(n0+row)*CC + kO + c16*8;
                cp16g(dst, gp);
            }
            CPA_ARRIVE(FULLB(s));
            s = (s==NSTG-1) ? 0 : s+1;
        }
        return;
    }

    const int warp = tid>>5, lane = tid&31, g = lane>>2, tg = lane&3;
    const int wm = (warp>>1)*32, wn = (warp&1)*64;

    const int lr = lane & 15;
    const int lc = lane >> 4;
    const int bn = (lane & 7) + ((lane & 16) ? 8 : 0);
    const int bc = (lane >> 3) & 1;
    const uint32_t aoff0 = (uint32_t)(((wm      + lr)*PITCH + lc*4)*4);
    const uint32_t aoff1 = (uint32_t)(((wm + 16 + lr)*PITCH + lc*4)*4);
    uint32_t boff[4];
    #pragma unroll
    for (int p=0;p<4;p++) boff[p] = (uint32_t)(((wn + p*16 + bn)*PITCH + bc*4)*4);
    const uint32_t dbase = sb + 1024;
    const uint32_t A4 = ARRW*4;

    float acc[2][8][4];
    #pragma unroll
    for (int a=0;a<2;a++)
        #pragma unroll
        for (int b=0;b<8;b++)
            #pragma unroll
            for (int c=0;c<4;c++) acc[a][b][c] = 0.f;

    int phf[NSTG] = {0,0,0};
    int s = 0;
    MBAR_WAIT(FULLB(0), 0); phf[0] = 1;
    for (int kt=0; kt<NK; kt++){
        const uint32_t stgb = dbase + s*(STGU*4);
        #pragma unroll
        for (int kk=0; kk<4; kk++){
            const uint32_t kb = kk*32;
            uint32_t ah0[4], ah1[4], al0[4], al1[4];
            LDSM4(ah0[0],ah0[1],ah0[2],ah0[3], stgb + aoff0 + kb);
            LDSM4(ah1[0],ah1[1],ah1[2],ah1[3], stgb + aoff1 + kb);
            LDSM4(al0[0],al0[1],al0[2],al0[3], stgb + A4 + aoff0 + kb);
            LDSM4(al1[0],al1[1],al1[2],al1[3], stgb + A4 + aoff1 + kb);
            uint32_t bh[4][4], bl[4][4];
            #pragma unroll
            for (int p=0;p<4;p++){
                LDSM4(bh[p][0],bh[p][1],bh[p][2],bh[p][3], stgb + 2*A4 + boff[p] + kb);
                LDSM4(bl[p][0],bl[p][1],bl[p][2],bl[p][3], stgb + 3*A4 + boff[p] + kb);
            }
            if (kk==3){
                MBAR_ARRIVE(EMPTYB(s));
                if (kt+1 < NK){
                    int ns = (s==NSTG-1) ? 0 : s+1;
                    MBAR_WAIT(FULLB(ns), phf[ns]); phf[ns] ^= 1;   // early wait, hidden by MMAs below
                }
            }
            #pragma unroll
            for (int p=0;p<4;p++){
                mma3b(acc[0][2*p  ], ah0, al0, bh[p][0], bh[p][1], bl[p][0], bl[p][1]);
                mma3b(acc[1][2*p  ], ah1, al1, bh[p][0], bh[p][1], bl[p][0], bl[p][1]);
                mma3b(acc[0][2*p+1], ah0, al0, bh[p][2], bh[p][3], bl[p][2], bl[p][3]);
                mma3b(acc[1][2*p+1], ah1, al1, bh[p][2], bh[p][3], bl[p][2], bl[p][3]);
            }
        }
        s = (s==NSTG-1) ? 0 : s+1;
    }

    const int b = m0 >> 7;
    const int head = nt;
    if (z < 2){
        __nv_bfloat16* dh = (z==0) ? g_Qhi : g_Khi;
        __nv_bfloat16* dl = (z==0) ? g_Qlo : g_Klo;
        #pragma unroll
        for (int mi=0; mi<2; mi++){
            #pragma unroll
            for (int ni=0; ni<8; ni++){
                int t = (wm + mi*16 + g);
                int sc = wn + ni*8 + tg*2;
                size_t idx = (((size_t)(b*HH + head))*TT + t)*HSD + sc;
                uint32_t h0, l0, h1, l1;
                split2(acc[mi][ni][0], acc[mi][ni][1], h0, l0);
                split2(acc[mi][ni][2], acc[mi][ni][3], h1, l1);
                *(uint32_t*)(dh + idx) = h0;
                *(uint32_t*)(dl + idx) = l0;
                *(uint32_t*)(dh + idx + 8*HSD) = h1;
                *(uint32_t*)(dl + idx + 8*HSD) = l1;
            }
        }
    } else {
        float* sT = (float*)(sm + 256);
        BARC(1, 256);
        #pragma unroll
        for (int mi=0; mi<2; mi++){
            #pragma unroll
            for (int ni=0; ni<8; ni++){
                int t = wm + mi*16 + g;
                int sc = wn + ni*8 + tg*2;
                sT[sc*132 + t]       = acc[mi][ni][0];
                sT[(sc+1)*132 + t]   = acc[mi][ni][1];
                sT[sc*132 + t+8]     = acc[mi][ni][2];
                sT[(sc+1)*132 + t+8] = acc[mi][ni][3];
            }
        }
        BARC(1, 256);
        __nv_bfloat16* vh = g_VThi + (((size_t)(b*HH + head))*HSD)*TT;
        __nv_bfloat16* vl = g_VTlo + (((size_t)(b*HH + head))*HSD)*TT;
        #pragma unroll
        for (int i=0;i<16;i++){
            int idx = tid + i*256;
            int sc = idx>>5, t4 = (idx&31)*4;
            float4 v = *(const float4*)&sT[sc*132 + t4];
            uint32_t h0,l0,h1,l1;
            split2(v.x, v.y, h0, l0);
            split2(v.z, v.w, h1, l1);
            uint2 hv; hv.x = h0; hv.y = h1;
            uint2 lv; lv.x = l0; lv.y = l1;
            *(uint2*)(vh + (size_t)sc*TT + t4) = hv;
            *(uint2*)(vl + (size_t)sc*TT + t4) = lv;
        }
    }
}

// ---------------------------------------------------------------------------
// Proj: warp-specialized SINGLE-TF32 GEMM.  C = att^T @ wp^T + bias.
// A = g_att (tf32 f32 bits), B = g_Ptf. CTA 128x128, K-tile 32, 4 stages.
// ---------------------------------------------------------------------------
#define TARR  (128*36)
#define TSTG  (2*TARR)
#define TNST  4

__global__ __launch_bounds__(384, 1)
void gemm_tf(const float* __restrict__ bias, float* __restrict__ Cout)
{
    extern __shared__ uint32_t sm[];
    const uint32_t sb = smem_u32(sm);
    const int tid = threadIdx.x;
    const int lid = blockIdx.x;
    const int pid = lid >> 8, rem = lid & 255;
    const int mt = pid*8 + (rem & 7), nt = rem >> 3;
    const int m0 = mt*128, n0 = nt*128;

    if (tid==0){
        #pragma unroll
        for (int s=0;s<TNST;s++){ MBAR_INIT(FULLB(s), 128); MBAR_INIT(EMPTYB(s), 256); }
    }
    __syncthreads();

    const int NK = CC/32;   // 128

    if (tid >= 256){
        const int pt = tid - 256;
        int ph[TNST] = {1,1,1,1};
        int s = 0;
        for (int kt=0; kt<NK; kt++){
            MBAR_WAIT(EMPTYB(s), ph[s]); ph[s] ^= 1;
            uint32_t* base = sm + 256 + s*TSTG;
            const size_t kO = (size_t)kt*32;
            #pragma unroll
            for (int j=0;j<16;j++){
                int id = pt + j*128;
                int arr = id >> 10;
                int c   = id & 1023;
                int row = c >> 3, c4 = c & 7;
                uint32_t* dst = base + arr*TARR + row*36 + c4*4;
                const uint32_t* gp = (arr==0)
                    ? g_att + (size_t)(m0+row)*CC + kO + c4*4
                    : g_Ptf + (size_t)(n0+row)*CC + kO + c4*4;
                cp16g(dst, gp);
            }
            CPA_ARRIVE(FULLB(s));
            s = (s+1) & 3;
        }
        return;
    }

    const int warp = tid>>5, lane = tid&31, g = lane>>2, tg = lane&3;
    const int wm = (warp>>1)*32, wn = (warp&1)*64;

    float acc[2][8][4];
    #pragma unroll
    for (int a=0;a<2;a++)
        #pragma unroll
        for (int b=0;b<8;b++)
            #pragma unroll
            for (int c=0;c<4;c++) acc[a][b][c] = 0.f;

    int phf[TNST] = {0,0,0,0};
    int s = 0;
    MBAR_WAIT(FULLB(0), 0); phf[0] = 1;
    for (int kt=0; kt<NK; kt++){
        const uint32_t* sA = sm + 256 + s*TSTG;
        const uint32_t* sB = sA + TARR;
        #pragma unroll
        for (int ks8=0; ks8<3; ks8++){
            const int q = ks8*8;
            uint32_t af[2][4];
            #pragma unroll
            for (int mi=0; mi<2; mi++){
                int r = wm + mi*16 + g;
                af[mi][0]=sA[r*36+q+tg];     af[mi][1]=sA[(r+8)*36+q+tg];
                af[mi][2]=sA[r*36+q+tg+4];   af[mi][3]=sA[(r+8)*36+q+tg+4];
            }
            #pragma unroll
            for (int ni=0; ni<8; ni++){
                int n = wn + ni*8 + g;
                uint32_t b0 = sB[n*36+q+tg], b1 = sB[n*36+q+tg+4];
                mma_tf32(acc[0][ni], af[0], b0, b1);
                mma_tf32(acc[1][ni], af[1], b0, b1);
            }
        }
        {   // last k8 block: hoist loads, then release+early-wait, then MMAs
            const int q = 24;
            uint32_t af[2][4];
            #pragma unroll
            for (int mi=0; mi<2; mi++){
                int r = wm + mi*16 + g;
                af[mi][0]=sA[r*36+q+tg];     af[mi][1]=sA[(r+8)*36+q+tg];
                af[mi][2]=sA[r*36+q+tg+4];   af[mi][3]=sA[(r+8)*36+q+tg+4];
            }
            uint32_t b0s[8], b1s[8];
            #pragma unroll
            for (int ni=0; ni<8; ni++){
                int n = wn + ni*8 + g;
                b0s[ni] = sB[n*36+q+tg]; b1s[ni] = sB[n*36+q+tg+4];
            }
            MBAR_ARRIVE(EMPTYB(s));
            if (kt+1 < NK){
                int ns = (s+1) & 3;
                MBAR_WAIT(FULLB(ns), phf[ns]); phf[ns] ^= 1;
            }
            #pragma unroll
            for (int ni=0; ni<8; ni++){
                mma_tf32(acc[0][ni], af[0], b0s[ni], b1s[ni]);
                mma_tf32(acc[1][ni], af[1], b0s[ni], b1s[ni]);
            }
        }
        s = (s+1) & 3;
    }

    #pragma unroll
    for (int mi=0; mi<2; mi++){
        #pragma unroll
        for (int ni=0; ni<8; ni++){
            int mrow = m0 + wm + mi*16 + g;
            int ncol = n0 + wn + ni*8 + tg*2;
            float bv0 = bias[ncol], bv1 = bias[ncol+1];
            float* p = Cout + (size_t)mrow*CC + ncol;
            p[0] = acc[mi][ni][0] + bv0; p[1] = acc[mi][ni][1] + bv1;
            p[8*CC] = acc[mi][ni][2] + bv0; p[8*CC+1] = acc[mi][ni][3] + bv1;
        }
    }
}

// ---------------------------------------------------------------------------
// Attention, all-bf16 3-term: QK^T -> softmax over QUERY axis -> P@V.
// Epilogue writes att^T as tf32-rounded f32 into g_att.
// ---------------------------------------------------------------------------
#define APITCH 68
#define AARR   (128*APITCH)
__global__ __launch_bounds__(256)
void attn_kernel()
{
    extern __shared__ uint32_t smu[];
    const uint32_t sb = smem_u32(smu);
    float* sW = (float*)(smu + 4*AARR);     // [t][132]

    const int tid = threadIdx.x;
    const int bid = blockIdx.x;
    const int bh = bid;
    const __nv_bfloat16* qh = g_Qhi + (size_t)bh*TT*HSD;
    const __nv_bfloat16* ql = g_Qlo + (size_t)bh*TT*HSD;
    const __nv_bfloat16* kh = g_Khi + (size_t)bh*TT*HSD;
    const __nv_bfloat16* kl = g_Klo + (size_t)bh*TT*HSD;

    #pragma unroll
    for (int i=0;i<32;i++){
        int idx = tid + i*256;
        int arr = idx >> 11;
        int c   = idx & 2047;
        int row = c >> 4, ch = c & 15;
        uint32_t* dst = smu + arr*AARR + row*APITCH + ch*4;
        const __nv_bfloat16* gp =
            (arr==0) ? qh + (size_t)row*HSD + ch*8 :
            (arr==1) ? ql + (size_t)row*HSD + ch*8 :
            (arr==2) ? kh + (size_t)row*HSD + ch*8 :
                       kl + (size_t)row*HSD + ch*8;
        cp16g(dst, gp);
    }
    CP_COMMIT(); CP_WAIT0();
    __syncthreads();

    const int warp = tid>>5, lane = tid&31, g = lane>>2, tg = lane&3;
    const int wm = (warp>>1)*32, wn = (warp&1)*64;
    const int lr = lane & 15;
    const int lc = lane >> 4;
    const int bn = (lane & 7) + ((lane & 16) ? 8 : 0);
    const int bc = (lane >> 3) & 1;
    const uint32_t aoff0 = (uint32_t)(((wm      + lr)*APITCH + lc*4)*4);
    const uint32_t aoff1 = (uint32_t)(((wm + 16 + lr)*APITCH + lc*4)*4);
    uint32_t boff[4];
    #pragma unroll
    for (int p=0;p<4;p++) boff[p] = (uint32_t)(((wn + p*16 + bn)*APITCH + bc*4)*4);
    const uint32_t A1 = AARR*4;

    // ---- QK^T: A = Q (arrays 0,1), B = K (arrays 2,3) ----
    {
        float acc[2][8][4];
        #pragma unroll
        for (int a=0;a<2;a++)
            #pragma unroll
            for (int c2=0;c2<8;c2++)
                #pragma unroll
                for (int d2=0;d2<4;d2++) acc[a][c2][d2]=0.f;
        #pragma unroll
        for (int kk=0; kk<8; kk++){
            const uint32_t kb = kk*32;
            uint32_t ah0[4], ah1[4], al0[4], al1[4];
            LDSM4(ah0[0],ah0[1],ah0[2],ah0[3], sb + aoff0 + kb);
            LDSM4(ah1[0],ah1[1],ah1[2],ah1[3], sb + aoff1 + kb);
            LDSM4(al0[0],al0[1],al0[2],al0[3], sb + A1 + aoff0 + kb);
            LDSM4(al1[0],al1[1],al1[2],al1[3], sb + A1 + aoff1 + kb);
            uint32_t bhf[4][4], blf[4][4];
            #pragma unroll
            for (int p=0;p<4;p++){
                LDSM4(bhf[p][0],bhf[p][1],bhf[p][2],bhf[p][3], sb + 2*A1 + boff[p] + kb);
                LDSM4(blf[p][0],blf[p][1],blf[p][2],blf[p][3], sb + 3*A1 + boff[p] + kb);
            }
            #pragma unroll
            for (int p=0;p<4;p++){
                mma3b(acc[0][2*p  ], ah0, al0, bhf[p][0], bhf[p][1], blf[p][0], blf[p][1]);
                mma3b(acc[1][2*p  ], ah1, al1, bhf[p][0], bhf[p][1], blf[p][0], blf[p][1]);
                mma3b(acc[0][2*p+1], ah0, al0, bhf[p][2], bhf[p][3], blf[p][2], blf[p][3]);
                mma3b(acc[1][2*p+1], ah1, al1, bhf[p][2], bhf[p][3], blf[p][2], blf[p][3]);
            }
        }
        #pragma unroll
        for (int mi=0; mi<2; mi++){
            #pragma unroll
            for (int ni=0; ni<8; ni++){
                int r = wm + mi*16 + g;
                int c = wn + ni*8 + tg*2;
                sW[r*132+c]       = acc[mi][ni][0]*SCALE;
                sW[r*132+c+1]     = acc[mi][ni][1]*SCALE;
                sW[(r+8)*132+c]   = acc[mi][ni][2]*SCALE;
                sW[(r+8)*132+c+1] = acc[mi][ni][3]*SCALE;
            }
        }
    }
    __syncthreads();

    if (tid < 128){
        const int u = tid;
        float mx = -1e30f;
        for (int t=0;t<128;t++) mx = fmaxf(mx, sW[t*132+u]);
        float ssum = 0.f;
        for (int t=0;t<128;t++){ float e = __expf(sW[t*132+u]-mx); sW[t*132+u]=e; ssum+=e; }
        float inv = 1.f/ssum;
        for (int t=0;t<128;t++) sW[t*132+u] *= inv;
    } else {
        const int lt = tid - 128;
        const __nv_bfloat16* vh = g_VThi + (size_t)bh*HSD*TT;
        const __nv_bfloat16* vl = g_VTlo + (size_t)bh*HSD*TT;
        #pragma unroll
        for (int i=0;i<32;i++){
            int idx = lt + i*128;
            int arr = idx >> 11;
            int c   = idx & 2047;
            int row = c >> 4, ch = c & 15;
            uint32_t* dst = smu + arr*AARR + row*APITCH + ch*4;
            const __nv_bfloat16* gp = (arr==0)
                ? vh + (size_t)row*TT + ch*8
                : vl + (size_t)row*TT + ch*8;
            cp16g(dst, gp);
        }
        CP_COMMIT(); CP_WAIT0();
    }
    __syncthreads();

    // convert W f32 -> bf16 hi/lo into K region (arrays 2,3)
    {
        int r = tid >> 1, half = tid & 1;
        uint32_t* wh = smu + 2*AARR + r*APITCH + half*32;
        uint32_t* wl = smu + 3*AARR + r*APITCH + half*32;
        const float* src = sW + r*132 + half*64;
        #pragma unroll
        for (int j=0;j<32;j++){
            uint32_t hi, lo;
            split2(src[2*j], src[2*j+1], hi, lo);
            wh[j] = hi; wl[j] = lo;
        }
    }
    __syncthreads();

    // ---- P@V: A = W (arrays 2,3), B = V^T (arrays 0,1) ----
    {
        float acc[2][8][4];
        #pragma unroll
        for (int a=0;a<2;a++)
            #pragma unroll
            for (int c2=0;c2<8;c2++)
                #pragma unroll
                for (int d2=0;d2<4;d2++) acc[a][c2][d2]=0.f;
        #pragma unroll
        for (int kk=0; kk<8; kk++){
            const uint32_t kb = kk*32;
            uint32_t ah0[4], ah1[4], al0[4], al1[4];
            LDSM4(ah0[0],ah0[1],ah0[2],ah0[3], sb + 2*A1 + aoff0 + kb);
            LDSM4(ah1[0],ah1[1],ah1[2],ah1[3], sb + 2*A1 + aoff1 + kb);
            LDSM4(al0[0],al0[1],al0[2],al0[3], sb + 3*A1 + aoff0 + kb);
            LDSM4(al1[0],al1[1],al1[2],al1[3], sb + 3*A1 + aoff1 + kb);
            uint32_t bhf[4][4], blf[4][4];
            #pragma unroll
            for (int p=0;p<4;p++){
                LDSM4(bhf[p][0],bhf[p][1],bhf[p][2],bhf[p][3], sb + boff[p] + kb);
                LDSM4(blf[p][0],blf[p][1],blf[p][2],blf[p][3], sb + A1 + boff[p] + kb);
            }
            #pragma unroll
            for (int p=0;p<4;p++){
                mma3b(acc[0][2*p  ], ah0, al0, bhf[p][0], bhf[p][1], blf[p][0], blf[p][1]);
                mma3b(acc[1][2*p  ], ah1, al1, bhf[p][0], bhf[p][1], blf[p][0], blf[p][1]);
                mma3b(acc[0][2*p+1], ah0, al0, bhf[p][2], bhf[p][3], blf[p][2], blf[p][3]);
                mma3b(acc[1][2*p+1], ah1, al1, bhf[p][2], bhf[p][3], blf[p][2], blf[p][3]);
            }
        }
        __syncthreads();
        // transpose-stage out[t][s] -> sW[s][t]
        #pragma unroll
        for (int mi=0; mi<2; mi++){
            #pragma unroll
            for (int ni=0; ni<8; ni++){
                int r = wm + mi*16 + g;
                int c = wn + ni*8 + tg*2;
                sW[c*132 + r]       = acc[mi][ni][0];
                sW[(c+1)*132 + r]   = acc[mi][ni][1];
                sW[c*132 + r+8]     = acc[mi][ni][2];
                sW[(c+1)*132 + r+8] = acc[mi][ni][3];
            }
        }
    }
    __syncthreads();

    // att^T[b*128+s][h*128+t] as tf32-rounded f32
    const int h = bid & 31, b = bid >> 5;
    uint32_t* oa = g_att + (size_t)(b*128)*CC + h*128;
    #pragma unroll
    for (int i=0;i<16;i++){
        int idx = tid + i*256;
        int sc = idx>>5, t4 = (idx&31)*4;
        float4 v = *(const float4*)&sW[sc*132 + t4];
        uint4 o;
        o.x = f2tf32(v.x); o.y = f2tf32(v.y);
        o.z = f2tf32(v.z); o.w = f2tf32(v.w);
        *(uint4*)&oa[(size_t)sc*CC + t4] = o;
    }
}

extern "C" void kernel_launch(void* const* d_in, const int* in_sizes, int n_in,
                              void* d_out, int out_size)
{
    const float* x  = (const float*)d_in[0];
    const float* wq = (const float*)d_in[1];
    const float* wk = (const float*)d_in[2];
    const float* wv = (const float*)d_in[3];
    const float* wp = (const float*)d_in[4];
    const float* bp = (const float*)d_in[5];
    float* out = (float*)d_out;

    const int smemG = (256 + NSTG*STGU)*4;          // 222208 B
    const int smemT = (256 + TNST*TSTG)*4;          // 148480 B
    const int smemA = (4*AARR + 128*132)*4;         // 206848 B
    cudaFuncSetAttribute(gemm_bf, cudaFuncAttributeMaxDynamicSharedMemorySize, smemG);
    cudaFuncSetAttribute(gemm_tf, cudaFuncAttributeMaxDynamicSharedMemorySize, smemT);
    cudaFuncSetAttribute(attn_kernel, cudaFuncAttributeMaxDynamicSharedMemorySize, smemA);

    conv_x<<<16384, 256>>>(x);                             // x -> Xhi/Xlo
    conv_wT<<<dim3(4,128,96), dim3(32,8)>>>(wq, wk, wv);   // w -> Whi/Wlo (transposed)
    conv_tf<<<8192, 256>>>(wp);                            // wp -> g_Ptf (tf32)
    gemm_bf<<<dim3(2048,1,3), 384, smemG>>>();             // QKV (bf16 out, V transposed)
    attn_kernel<<<2048, 256, smemA>>>();                   // attention -> g_att (tf32)
    gemm_tf<<<2048, 384, smemT>>>(bp, out);                // proj single-tf32
}